// round 1
// baseline (speedup 1.0000x reference)
#include <cuda_runtime.h>
#include <math.h>

// Problem constants (fixed by the reference)
#define H_DIM 2048
#define I_DIM 4096
#define E_NUM 8
#define T_NUM 4096   // B*S = 2*2048
#define TOPK  2

// Tiling
#define TM 128
#define TN 128
#define TKK 8

// ---------------- scratch (allocation-free: __device__ globals) ----------------
__device__ int   g_tok[T_NUM * TOPK];                 // token id per (expert,slot) entry
__device__ float g_wgt[T_NUM * TOPK];                 // combined routing weight
__device__ int   g_cnt[E_NUM];
__device__ int   g_off[E_NUM + 1];
__device__ float g_inter[33554432UL];                 // 8192 rows x 4096 (I) = 128 MB

// ---------------- routing ----------------
// expert_indices may materialize as int32 (JAX x64 off) or int64.
// Detection: interpret as 32-bit words; words at odd positions within the first
// 8192 words are all zero iff layout is int64 (values are 0..7).
__global__ void route_kernel(const unsigned* __restrict__ idx_raw,
                             const float* __restrict__ wts)
{
    __shared__ int s_flag;
    __shared__ int s_cnt[E_NUM];
    __shared__ int s_off[E_NUM + 1];
    const int tid = threadIdx.x;

    if (tid == 0) s_flag = 0;
    __syncthreads();

    unsigned acc = 0;
    for (int i = 1 + 2 * tid; i < T_NUM * TOPK; i += 2 * 256)
        acc |= idx_raw[i];
    if (acc) atomicOr(&s_flag, 1);
    __syncthreads();
    const int is64 = (s_flag == 0) ? 1 : 0;

    // Pass 1: count entries per expert (sequential per-expert scan -> deterministic)
    if (tid < E_NUM) {
        const int e = tid;
        int c = 0;
        for (int t = 0; t < T_NUM; t++) {
            int e0 = is64 ? (int)idx_raw[4 * t]     : (int)idx_raw[2 * t];
            int e1 = is64 ? (int)idx_raw[4 * t + 2] : (int)idx_raw[2 * t + 1];
            if (e0 == e || e1 == e) c++;
        }
        s_cnt[e] = c;
    }
    __syncthreads();

    if (tid == 0) {
        int o = 0;
        for (int e = 0; e < E_NUM; e++) {
            s_off[e] = o; g_off[e] = o; g_cnt[e] = s_cnt[e];
            o += s_cnt[e];
        }
        s_off[E_NUM] = o; g_off[E_NUM] = o;
    }
    __syncthreads();

    // Pass 2: place entries in token order (duplicate slots merge weights,
    // matching the reference's one-hot weight sum)
    if (tid < E_NUM) {
        const int e = tid;
        int p = s_off[e];
        for (int t = 0; t < T_NUM; t++) {
            int e0 = is64 ? (int)idx_raw[4 * t]     : (int)idx_raw[2 * t];
            int e1 = is64 ? (int)idx_raw[4 * t + 2] : (int)idx_raw[2 * t + 1];
            if (e0 == e || e1 == e) {
                float w = 0.0f;
                if (e0 == e) w += wts[2 * t];
                if (e1 == e) w += wts[2 * t + 1];
                g_tok[p] = t;
                g_wgt[p] = w;
                p++;
            }
        }
    }
}

// ---------------- GEMM 1: inter = silu(Xg @ G^T) * (Xg @ U^T), gathered rows ----------------
__global__ void __launch_bounds__(256, 1)
gemm1_kernel(const float* __restrict__ x,
             const float* __restrict__ gate,
             const float* __restrict__ up)
{
    const int e = blockIdx.z;
    const int cnt = g_cnt[e];
    const int rowBase = blockIdx.y * TM;
    if (rowBase >= cnt) return;
    const int off = g_off[e];
    const int n0 = blockIdx.x * TN;

    __shared__ __align__(16) float As[TKK][TM];
    __shared__ __align__(16) float Gs[TKK][TN];
    __shared__ __align__(16) float Us[TKK][TN];
    __shared__ int s_tok[TM];

    const int tid = threadIdx.x;
    if (tid < TM) {
        int r = rowBase + tid;
        s_tok[tid] = (r < cnt) ? g_tok[off + r] : -1;
    }
    __syncthreads();

    const int lr = tid >> 1;            // 0..127: tile row loaded by this thread
    const int lk = (tid & 1) << 2;      // 0 or 4: k sub-offset (float4)
    const int tokid = s_tok[lr];
    const bool avalid = (tokid >= 0);
    const float* aptr = x + (size_t)(avalid ? tokid : 0) * H_DIM + lk;
    const float* gptr = gate + ((size_t)e * I_DIM + n0 + lr) * H_DIM + lk;
    const float* uptr = up   + ((size_t)e * I_DIM + n0 + lr) * H_DIM + lk;

    const int tx = tid & 15, ty = tid >> 4;
    const int tm = ty * 8, tn = tx * 8;

    float accG[8][8];
    float accU[8][8];
#pragma unroll
    for (int i = 0; i < 8; i++)
#pragma unroll
        for (int j = 0; j < 8; j++) { accG[i][j] = 0.0f; accU[i][j] = 0.0f; }

    float4 av = avalid ? *(const float4*)(aptr) : make_float4(0.f, 0.f, 0.f, 0.f);
    float4 gv = *(const float4*)(gptr);
    float4 uv = *(const float4*)(uptr);

    for (int kk = 0; kk < H_DIM; kk += TKK) {
        As[lk + 0][lr] = av.x; As[lk + 1][lr] = av.y; As[lk + 2][lr] = av.z; As[lk + 3][lr] = av.w;
        Gs[lk + 0][lr] = gv.x; Gs[lk + 1][lr] = gv.y; Gs[lk + 2][lr] = gv.z; Gs[lk + 3][lr] = gv.w;
        Us[lk + 0][lr] = uv.x; Us[lk + 1][lr] = uv.y; Us[lk + 2][lr] = uv.z; Us[lk + 3][lr] = uv.w;
        __syncthreads();

        const int kn = kk + TKK;
        if (kn < H_DIM) {
            av = avalid ? *(const float4*)(aptr + kn) : make_float4(0.f, 0.f, 0.f, 0.f);
            gv = *(const float4*)(gptr + kn);
            uv = *(const float4*)(uptr + kn);
        }

#pragma unroll
        for (int k = 0; k < TKK; k++) {
            float a[8], b[8], c[8];
            *(float4*)(a)     = *(const float4*)(&As[k][tm]);
            *(float4*)(a + 4) = *(const float4*)(&As[k][tm + 4]);
            *(float4*)(b)     = *(const float4*)(&Gs[k][tn]);
            *(float4*)(b + 4) = *(const float4*)(&Gs[k][tn + 4]);
            *(float4*)(c)     = *(const float4*)(&Us[k][tn]);
            *(float4*)(c + 4) = *(const float4*)(&Us[k][tn + 4]);
#pragma unroll
            for (int i = 0; i < 8; i++)
#pragma unroll
                for (int j = 0; j < 8; j++) {
                    accG[i][j] = fmaf(a[i], b[j], accG[i][j]);
                    accU[i][j] = fmaf(a[i], c[j], accU[i][j]);
                }
        }
        __syncthreads();
    }

    // Epilogue: inter = silu(g) * u, vectorized float4 stores
#pragma unroll
    for (int i = 0; i < 8; i++) {
        int r = rowBase + tm + i;
        if (r >= cnt) continue;
        float* dst = &g_inter[(size_t)(off + r) * I_DIM + n0 + tn];
#pragma unroll
        for (int j4 = 0; j4 < 8; j4 += 4) {
            float4 v;
            float* pv = (float*)&v;
#pragma unroll
            for (int l = 0; l < 4; l++) {
                float g = accG[i][j4 + l];
                float u = accU[i][j4 + l];
                float s = g / (1.0f + expf(-g));
                pv[l] = s * u;
            }
            *(float4*)(dst + j4) = v;
        }
    }
}

// ---------------- GEMM 2: out[tok] += w * (inter @ D^T), scatter-add ----------------
__global__ void __launch_bounds__(256, 1)
gemm2_kernel(const float* __restrict__ down, float* __restrict__ out)
{
    const int e = blockIdx.z;
    const int cnt = g_cnt[e];
    const int rowBase = blockIdx.y * TM;
    if (rowBase >= cnt) return;
    const int off = g_off[e];
    const int n0 = blockIdx.x * TN;

    __shared__ __align__(16) float As[TKK][TM];
    __shared__ __align__(16) float Bs[TKK][TN];
    __shared__ int   s_tok[TM];
    __shared__ float s_wgt[TM];

    const int tid = threadIdx.x;
    if (tid < TM) {
        int r = rowBase + tid;
        s_tok[tid] = (r < cnt) ? g_tok[off + r] : 0;
        s_wgt[tid] = (r < cnt) ? g_wgt[off + r] : 0.0f;
    }

    const int lr = tid >> 1;
    const int lk = (tid & 1) << 2;
    const int r_a = rowBase + lr;
    const bool avalid = (r_a < cnt);
    const float* aptr = g_inter + (size_t)(off + (avalid ? r_a : 0)) * I_DIM + lk;
    const float* bptr = down + ((size_t)e * H_DIM + n0 + lr) * I_DIM + lk;

    const int tx = tid & 15, ty = tid >> 4;
    const int tm = ty * 8, tn = tx * 8;

    float acc[8][8];
#pragma unroll
    for (int i = 0; i < 8; i++)
#pragma unroll
        for (int j = 0; j < 8; j++) acc[i][j] = 0.0f;

    float4 av = *(const float4*)(aptr);
    float4 bv = *(const float4*)(bptr);

    for (int kk = 0; kk < I_DIM; kk += TKK) {
        As[lk + 0][lr] = av.x; As[lk + 1][lr] = av.y; As[lk + 2][lr] = av.z; As[lk + 3][lr] = av.w;
        Bs[lk + 0][lr] = bv.x; Bs[lk + 1][lr] = bv.y; Bs[lk + 2][lr] = bv.z; Bs[lk + 3][lr] = bv.w;
        __syncthreads();

        const int kn = kk + TKK;
        if (kn < I_DIM) {
            av = *(const float4*)(aptr + kn);
            bv = *(const float4*)(bptr + kn);
        }

#pragma unroll
        for (int k = 0; k < TKK; k++) {
            float a[8], b[8];
            *(float4*)(a)     = *(const float4*)(&As[k][tm]);
            *(float4*)(a + 4) = *(const float4*)(&As[k][tm + 4]);
            *(float4*)(b)     = *(const float4*)(&Bs[k][tn]);
            *(float4*)(b + 4) = *(const float4*)(&Bs[k][tn + 4]);
#pragma unroll
            for (int i = 0; i < 8; i++)
#pragma unroll
                for (int j = 0; j < 8; j++)
                    acc[i][j] = fmaf(a[i], b[j], acc[i][j]);
        }
        __syncthreads();
    }

    // Epilogue: weighted scatter-add into out (<=2 contributions per token row)
#pragma unroll
    for (int i = 0; i < 8; i++) {
        int r = rowBase + tm + i;
        if (r >= cnt) continue;
        int t = s_tok[tm + i];
        float w = s_wgt[tm + i];
        float* dst = out + (size_t)t * H_DIM + n0 + tn;
#pragma unroll
        for (int j = 0; j < 8; j++)
            atomicAdd(dst + j, w * acc[i][j]);
    }
}

// ---------------- launch ----------------
extern "C" void kernel_launch(void* const* d_in, const int* in_sizes, int n_in,
                              void* d_out, int out_size)
{
    const float*    x    = (const float*)d_in[0];
    const unsigned* idx  = (const unsigned*)d_in[1];
    const float*    wts  = (const float*)d_in[2];
    const float*    gate = (const float*)d_in[3];
    const float*    up   = (const float*)d_in[4];
    const float*    down = (const float*)d_in[5];
    float* out = (float*)d_out;

    cudaMemsetAsync(out, 0, (size_t)out_size * sizeof(float));
    route_kernel<<<1, 256>>>(idx, wts);
    gemm1_kernel<<<dim3(I_DIM / TN, T_NUM / TM, E_NUM), 256>>>(x, gate, up);
    gemm2_kernel<<<dim3(H_DIM / TN, T_NUM / TM, E_NUM), 256>>>(down, out);
}

// round 4
// speedup vs baseline: 2.2766x; 2.2766x over previous
#include <cuda_runtime.h>
#include <cuda_bf16.h>
#include <math.h>
#include <stdint.h>

// ---------------- problem constants ----------------
#define H_DIM 2048
#define I_DIM 4096
#define E_NUM 8
#define T_NUM 4096   // B*S
#define TOPK  2

#define TM 128       // CTA token-tile
#define TN 128       // CTA feature-tile
#define TK 32        // K elements per block
#define NTHREADS 512 // 16 warps, 4x4 warp grid, warp tile 32x32

#define RS 80        // SMEM row stride in bytes (32 bf16 = 64B + 16B pad)

// ---------------- scratch (__device__ globals: allocation-free) ----------------
__device__ int      g_tok[T_NUM * TOPK];
__device__ float    g_wgt[T_NUM * TOPK];
__device__ int      g_cnt[E_NUM];
__device__ int      g_off[E_NUM + 1];
// inter stored as packed (hi bf16 | lo bf16 << 16) per element: exact split reused by gemm2
__device__ uint32_t g_inter[(size_t)T_NUM * TOPK * I_DIM];   // 8192 x 4096 x 4B = 128MB

// ---------------- helpers ----------------
__device__ __forceinline__ uint32_t pack_split(float v) {
    __nv_bfloat16 h = __float2bfloat16(v);
    __nv_bfloat16 l = __float2bfloat16(v - __bfloat162float(h));
    uint16_t hu = __bfloat16_as_ushort(h);
    uint16_t lu = __bfloat16_as_ushort(l);
    return (uint32_t)hu | ((uint32_t)lu << 16);
}

__device__ __forceinline__ void ld8f(const float* p, float* v) {
    float4 a = *(const float4*)p;
    float4 b = *(const float4*)(p + 4);
    v[0] = a.x; v[1] = a.y; v[2] = a.z; v[3] = a.w;
    v[4] = b.x; v[5] = b.y; v[6] = b.z; v[7] = b.w;
}

// split 8 fp32 -> hi/lo bf16, store 16B each into padded SMEM tiles
__device__ __forceinline__ void split8_sts(const float* v, char* s_hi, char* s_lo, int boff) {
    union { __nv_bfloat16 h[8]; uint4 q; } hi, lo;
#pragma unroll
    for (int i = 0; i < 8; i++) {
        __nv_bfloat16 h = __float2bfloat16(v[i]);
        hi.h[i] = h;
        lo.h[i] = __float2bfloat16(v[i] - __bfloat162float(h));
    }
    *(uint4*)(s_hi + boff) = hi.q;
    *(uint4*)(s_lo + boff) = lo.q;
}

#define MMA(d, a, b0, b1) \
    asm volatile("mma.sync.aligned.m16n8k16.row.col.f32.bf16.bf16.f32 " \
        "{%0,%1,%2,%3}, {%4,%5,%6,%7}, {%8,%9}, {%0,%1,%2,%3};" \
        : "+f"((d)[0]), "+f"((d)[1]), "+f"((d)[2]), "+f"((d)[3]) \
        : "r"((a)[0]), "r"((a)[1]), "r"((a)[2]), "r"((a)[3]), "r"(b0), "r"(b1))

// load A fragment (m16k16) from padded SMEM: rows base_r.., k16 selects k half
__device__ __forceinline__ void lda(uint32_t* a, const char* s, int base_r, int lr, int lc2, int k16) {
    int b = (base_r + lr) * RS + k16 * 32 + lc2;
    a[0] = *(const uint32_t*)(s + b);
    a[1] = *(const uint32_t*)(s + b + 8 * RS);
    a[2] = *(const uint32_t*)(s + b + 16);
    a[3] = *(const uint32_t*)(s + b + 8 * RS + 16);
}
// load B fragment (k16n8): row n holds K contiguously
__device__ __forceinline__ void ldb(uint32_t* b, const char* s, int base_n, int lr, int lc2, int k16) {
    int o = (base_n + lr) * RS + k16 * 32 + lc2;
    b[0] = *(const uint32_t*)(s + o);
    b[1] = *(const uint32_t*)(s + o + 16);
}

// ---------------- routing: warp-per-expert, ballot compaction ----------------
__global__ void route_kernel(const unsigned* __restrict__ idx_raw,
                             const float* __restrict__ wts)
{
    __shared__ int s_flag;
    __shared__ int s_cnt[E_NUM];
    __shared__ int s_off[E_NUM + 1];
    const int tid = threadIdx.x, wid = tid >> 5, lane = tid & 31;

    if (tid == 0) s_flag = 0;
    __syncthreads();
    unsigned acc = 0;
    for (int i = 1 + 2 * tid; i < T_NUM * TOPK; i += 512) acc |= idx_raw[i];
    if (acc) atomicOr(&s_flag, 1);
    __syncthreads();
    const int is64 = (s_flag == 0) ? 1 : 0;

    const int e = wid;
    int c = 0;
    for (int base = 0; base < T_NUM; base += 32) {
        int t = base + lane;
        int e0 = is64 ? (int)idx_raw[4 * t]     : (int)idx_raw[2 * t];
        int e1 = is64 ? (int)idx_raw[4 * t + 2] : (int)idx_raw[2 * t + 1];
        c += (e0 == e || e1 == e) ? 1 : 0;
    }
#pragma unroll
    for (int o = 16; o; o >>= 1) c += __shfl_down_sync(0xffffffffu, c, o);
    if (lane == 0) s_cnt[e] = c;
    __syncthreads();
    if (tid == 0) {
        int o = 0;
        for (int i = 0; i < E_NUM; i++) { s_off[i] = o; g_off[i] = o; g_cnt[i] = s_cnt[i]; o += s_cnt[i]; }
        s_off[E_NUM] = o; g_off[E_NUM] = o;
    }
    __syncthreads();
    int p = s_off[e];
    for (int base = 0; base < T_NUM; base += 32) {
        int t = base + lane;
        int e0 = is64 ? (int)idx_raw[4 * t]     : (int)idx_raw[2 * t];
        int e1 = is64 ? (int)idx_raw[4 * t + 2] : (int)idx_raw[2 * t + 1];
        bool m = (e0 == e || e1 == e);
        float w = (e0 == e ? wts[2 * t] : 0.0f) + (e1 == e ? wts[2 * t + 1] : 0.0f);
        unsigned msk = __ballot_sync(0xffffffffu, m);
        int pos = p + __popc(msk & ((1u << lane) - 1u));
        if (m) { g_tok[pos] = t; g_wgt[pos] = w; }
        p += __popc(msk);
    }
}

// ---------------- GEMM1: inter = silu(Xg Gt) * (Xg Ut), HMMA bf16x3 ----------------
// dynamic SMEM: s_tok [0,512), tiles at 1024: AHI ALO GHI GLO UHI ULO, 10240B each
#define T1_AHI 1024
#define T1_ALO (T1_AHI + TM * RS)
#define T1_GHI (T1_ALO + TM * RS)
#define T1_GLO (T1_GHI + TN * RS)
#define T1_UHI (T1_GLO + TN * RS)
#define T1_ULO (T1_UHI + TN * RS)
#define G1_SMEM (T1_ULO + TN * RS)

__global__ void __launch_bounds__(NTHREADS, 1)
gemm1_kernel(const float* __restrict__ x,
             const float* __restrict__ gate,
             const float* __restrict__ up)
{
    const int e = blockIdx.z;
    const int cnt = g_cnt[e];
    const int rowBase = blockIdx.y * TM;
    if (rowBase >= cnt) return;
    const int off = g_off[e];
    const int n0 = blockIdx.x * TN;

    extern __shared__ char smem[];
    int* s_tok = (int*)smem;
    char* sAH = smem + T1_AHI; char* sAL = smem + T1_ALO;
    char* sGH = smem + T1_GHI; char* sGL = smem + T1_GLO;
    char* sUH = smem + T1_UHI; char* sUL = smem + T1_ULO;

    const int tid = threadIdx.x, wid = tid >> 5, lane = tid & 31;
    const int wm = wid >> 2, wn = wid & 3;          // 4x4 warp grid
    const int lr = lane >> 2, lc2 = (lane & 3) << 2; // lc2 = byte offset of k-pair

    if (tid < TM) { int r = rowBase + tid; s_tok[tid] = (r < cnt) ? g_tok[off + r] : -1; }
    __syncthreads();

    // per-thread staging coords: row = tid>>2 (0..127), seg = tid&3 (8 floats each)
    const int srow = tid >> 2, sseg = tid & 3;
    const int sboff = srow * RS + sseg * 16;
    const int stok = s_tok[srow];
    const float* xp = (stok >= 0) ? (x + (size_t)stok * H_DIM + sseg * 8) : nullptr;
    const float* gp = gate + ((size_t)e * I_DIM + n0 + srow) * H_DIM + sseg * 8;
    const float* up_ = up  + ((size_t)e * I_DIM + n0 + srow) * H_DIM + sseg * 8;

    float accG[2][4][4], accU[2][4][4];
#pragma unroll
    for (int i = 0; i < 2; i++)
#pragma unroll
        for (int j = 0; j < 4; j++)
#pragma unroll
            for (int k = 0; k < 4; k++) { accG[i][j][k] = 0.0f; accU[i][j][k] = 0.0f; }

    for (int kk = 0; kk < H_DIM; kk += TK) {
        float v[8];
        if (xp) ld8f(xp + kk, v);
        else {
#pragma unroll
            for (int j = 0; j < 8; j++) v[j] = 0.0f;
        }
        split8_sts(v, sAH, sAL, sboff);
        ld8f(gp + kk, v);
        split8_sts(v, sGH, sGL, sboff);
        ld8f(up_ + kk, v);
        split8_sts(v, sUH, sUL, sboff);
        __syncthreads();

#pragma unroll
        for (int k16 = 0; k16 < 2; k16++) {
            uint32_t aH[2][4], aL[2][4];
#pragma unroll
            for (int mt = 0; mt < 2; mt++) {
                lda(aH[mt], sAH, wm * 32 + mt * 16, lr, lc2, k16);
                lda(aL[mt], sAL, wm * 32 + mt * 16, lr, lc2, k16);
            }
#pragma unroll
            for (int nt = 0; nt < 4; nt++) {
                uint32_t bgH[2], bgL[2], buH[2], buL[2];
                ldb(bgH, sGH, wn * 32 + nt * 8, lr, lc2, k16);
                ldb(bgL, sGL, wn * 32 + nt * 8, lr, lc2, k16);
                ldb(buH, sUH, wn * 32 + nt * 8, lr, lc2, k16);
                ldb(buL, sUL, wn * 32 + nt * 8, lr, lc2, k16);
#pragma unroll
                for (int mt = 0; mt < 2; mt++) {
                    MMA(accG[mt][nt], aH[mt], bgH[0], bgH[1]);
                    MMA(accG[mt][nt], aH[mt], bgL[0], bgL[1]);
                    MMA(accG[mt][nt], aL[mt], bgH[0], bgH[1]);
                    MMA(accU[mt][nt], aH[mt], buH[0], buH[1]);
                    MMA(accU[mt][nt], aH[mt], buL[0], buL[1]);
                    MMA(accU[mt][nt], aL[mt], buH[0], buH[1]);
                }
            }
        }
        __syncthreads();
    }

    // epilogue: silu(g)*u, packed split store to g_inter
#pragma unroll
    for (int mt = 0; mt < 2; mt++) {
#pragma unroll
        for (int half = 0; half < 2; half++) {
            int rloc = wm * 32 + mt * 16 + lr + half * 8;
            int r = rowBase + rloc;
            if (r >= cnt) continue;
            size_t base = (size_t)(off + r) * I_DIM + n0 + wn * 32;
#pragma unroll
            for (int nt = 0; nt < 4; nt++) {
                float g0 = accG[mt][nt][half * 2 + 0], u0 = accU[mt][nt][half * 2 + 0];
                float g1 = accG[mt][nt][half * 2 + 1], u1 = accU[mt][nt][half * 2 + 1];
                float v0 = (g0 / (1.0f + __expf(-g0))) * u0;
                float v1 = (g1 / (1.0f + __expf(-g1))) * u1;
                uint2 w = make_uint2(pack_split(v0), pack_split(v1));
                *(uint2*)(&g_inter[base + nt * 8 + (lc2 >> 1)]) = w;
            }
        }
    }
}

// ---------------- GEMM2: out[tok] += w * (inter Dt), HMMA bf16x3 ----------------
// dynamic SMEM: s_tok [0,512), s_wgt [512,1024), tiles at 1024: AHI ALO BHI BLO
#define T2_AHI 1024
#define T2_ALO (T2_AHI + TM * RS)
#define T2_BHI (T2_ALO + TM * RS)
#define T2_BLO (T2_BHI + TN * RS)
#define G2_SMEM (T2_BLO + TN * RS)

__global__ void __launch_bounds__(NTHREADS, 1)
gemm2_kernel(const float* __restrict__ down, float* __restrict__ out)
{
    const int e = blockIdx.z;
    const int cnt = g_cnt[e];
    const int rowBase = blockIdx.y * TM;
    if (rowBase >= cnt) return;
    const int off = g_off[e];
    const int n0 = blockIdx.x * TN;

    extern __shared__ char smem[];
    int*   s_tok = (int*)smem;
    float* s_wgt = (float*)(smem + 512);
    char* sAH = smem + T2_AHI; char* sAL = smem + T2_ALO;
    char* sBH = smem + T2_BHI; char* sBL = smem + T2_BLO;

    const int tid = threadIdx.x, wid = tid >> 5, lane = tid & 31;
    const int wm = wid >> 2, wn = wid & 3;
    const int lr = lane >> 2, lc2 = (lane & 3) << 2;

    if (tid < TM) {
        int r = rowBase + tid;
        s_tok[tid] = (r < cnt) ? g_tok[off + r] : -1;
        s_wgt[tid] = (r < cnt) ? g_wgt[off + r] : 0.0f;
    }
    __syncthreads();

    const int srow = tid >> 2, sseg = tid & 3;
    const int sboff = srow * RS + sseg * 16;
    const int arow = (rowBase + srow < cnt) ? (off + rowBase + srow) : off;
    const uint32_t* ap = g_inter + (size_t)arow * I_DIM + sseg * 8;
    const float* bp = down + ((size_t)e * H_DIM + n0 + srow) * I_DIM + sseg * 8;

    float acc[2][4][4];
#pragma unroll
    for (int i = 0; i < 2; i++)
#pragma unroll
        for (int j = 0; j < 4; j++)
#pragma unroll
            for (int k = 0; k < 4; k++) acc[i][j][k] = 0.0f;

    for (int kk = 0; kk < I_DIM; kk += TK) {
        // A: packed words -> hi/lo tiles
        uint4 w0 = *(const uint4*)(ap + kk);
        uint4 w1 = *(const uint4*)(ap + kk + 4);
        uint32_t ws[8] = { w0.x, w0.y, w0.z, w0.w, w1.x, w1.y, w1.z, w1.w };
        uint4 hi, lo;
        uint32_t* hp = (uint32_t*)&hi;
        uint32_t* lp = (uint32_t*)&lo;
#pragma unroll
        for (int i = 0; i < 4; i++) {
            uint32_t wa = ws[2 * i], wb = ws[2 * i + 1];
            hp[i] = (wa & 0xffffu) | ((wb & 0xffffu) << 16);
            lp[i] = (wa >> 16) | (wb & 0xffff0000u);
        }
        *(uint4*)(sAH + sboff) = hi;
        *(uint4*)(sAL + sboff) = lo;
        // B: fp32 -> split
        float v[8];
        ld8f(bp + kk, v);
        split8_sts(v, sBH, sBL, sboff);
        __syncthreads();

#pragma unroll
        for (int k16 = 0; k16 < 2; k16++) {
            uint32_t aH[2][4], aL[2][4];
#pragma unroll
            for (int mt = 0; mt < 2; mt++) {
                lda(aH[mt], sAH, wm * 32 + mt * 16, lr, lc2, k16);
                lda(aL[mt], sAL, wm * 32 + mt * 16, lr, lc2, k16);
            }
#pragma unroll
            for (int nt = 0; nt < 4; nt++) {
                uint32_t bH[2], bL[2];
                ldb(bH, sBH, wn * 32 + nt * 8, lr, lc2, k16);
                ldb(bL, sBL, wn * 32 + nt * 8, lr, lc2, k16);
#pragma unroll
                for (int mt = 0; mt < 2; mt++) {
                    MMA(acc[mt][nt], aH[mt], bH[0], bH[1]);
                    MMA(acc[mt][nt], aH[mt], bL[0], bL[1]);
                    MMA(acc[mt][nt], aL[mt], bH[0], bH[1]);
                }
            }
        }
        __syncthreads();
    }

    // epilogue: weighted scatter-add
#pragma unroll
    for (int mt = 0; mt < 2; mt++) {
#pragma unroll
        for (int half = 0; half < 2; half++) {
            int rloc = wm * 32 + mt * 16 + lr + half * 8;
            int t = s_tok[rloc];
            if (t < 0) continue;
            float w = s_wgt[rloc];
            float* dst = out + (size_t)t * H_DIM + n0 + wn * 32 + (lc2 >> 1);
#pragma unroll
            for (int nt = 0; nt < 4; nt++) {
                atomicAdd(dst + nt * 8 + 0, w * acc[mt][nt][half * 2 + 0]);
                atomicAdd(dst + nt * 8 + 1, w * acc[mt][nt][half * 2 + 1]);
            }
        }
    }
}

// ---------------- launch ----------------
extern "C" void kernel_launch(void* const* d_in, const int* in_sizes, int n_in,
                              void* d_out, int out_size)
{
    const float*    x    = (const float*)d_in[0];
    const unsigned* idx  = (const unsigned*)d_in[1];
    const float*    wts  = (const float*)d_in[2];
    const float*    gate = (const float*)d_in[3];
    const float*    up   = (const float*)d_in[4];
    const float*    down = (const float*)d_in[5];
    float* out = (float*)d_out;

    static int attr_done = 0;
    if (!attr_done) {
        cudaFuncSetAttribute(gemm1_kernel, cudaFuncAttributeMaxDynamicSharedMemorySize, G1_SMEM);
        cudaFuncSetAttribute(gemm2_kernel, cudaFuncAttributeMaxDynamicSharedMemorySize, G2_SMEM);
        attr_done = 1;
    }

    cudaMemsetAsync(out, 0, (size_t)out_size * sizeof(float));
    route_kernel<<<1, 256>>>(idx, wts);
    gemm1_kernel<<<dim3(I_DIM / TN, T_NUM / TM, E_NUM), NTHREADS, G1_SMEM>>>(x, gate, up);
    gemm2_kernel<<<dim3(H_DIM / TN, T_NUM / TM, E_NUM), NTHREADS, G2_SMEM>>>(down, out);
}

// round 5
// speedup vs baseline: 2.6652x; 1.1707x over previous
#include <cuda_runtime.h>
#include <cuda_bf16.h>
#include <stdint.h>

// ---------------- problem constants ----------------
#define H_DIM 2048
#define I_DIM 4096
#define E_NUM 8
#define T_NUM 4096   // B*S
#define TOPK  2

#define TM 128
#define TN 128
#define TK 32
#define NTHREADS 512
#define RS 80        // SMEM row stride bytes (32 bf16 = 64B + 16B pad)
#define NSTAGE 3

// ---------------- scratch (__device__ globals: allocation-free) ----------------
__device__ int   g_tok[T_NUM * TOPK];
__device__ float g_wgt[T_NUM * TOPK];
__device__ int   g_cnt[E_NUM];
__device__ int   g_off[E_NUM + 1];

#define NW ((size_t)E_NUM * I_DIM * H_DIM)   // 67.1M elements per weight tensor
__device__ __nv_bfloat16 g_xh[(size_t)T_NUM * H_DIM];
__device__ __nv_bfloat16 g_xl[(size_t)T_NUM * H_DIM];
__device__ __nv_bfloat16 g_gh[NW];
__device__ __nv_bfloat16 g_gl[NW];
__device__ __nv_bfloat16 g_uh[NW];
__device__ __nv_bfloat16 g_ul[NW];
__device__ __nv_bfloat16 g_dh[NW];
__device__ __nv_bfloat16 g_dl[NW];
__device__ __nv_bfloat16 g_ih[(size_t)T_NUM * TOPK * I_DIM];  // inter hi
__device__ __nv_bfloat16 g_il[(size_t)T_NUM * TOPK * I_DIM];  // inter lo

// ---------------- helpers ----------------
__device__ __forceinline__ void cpa16(uint32_t dst, const void* src, int srcsz) {
    asm volatile("cp.async.cg.shared.global [%0], [%1], 16, %2;"
                 :: "r"(dst), "l"(src), "r"(srcsz) : "memory");
}
#define CP_COMMIT() asm volatile("cp.async.commit_group;" ::: "memory")
#define CP_WAIT1()  asm volatile("cp.async.wait_group 1;" ::: "memory")
#define CP_WAIT0()  asm volatile("cp.async.wait_group 0;" ::: "memory")

__device__ __forceinline__ uint32_t smem_u32(const void* p) {
    uint32_t a;
    asm("{ .reg .u64 t; cvta.to.shared.u64 t, %1; cvt.u32.u64 %0, t; }" : "=r"(a) : "l"(p));
    return a;
}

#define MMA(d, a, b0, b1) \
    asm volatile("mma.sync.aligned.m16n8k16.row.col.f32.bf16.bf16.f32 " \
        "{%0,%1,%2,%3}, {%4,%5,%6,%7}, {%8,%9}, {%0,%1,%2,%3};" \
        : "+f"((d)[0]), "+f"((d)[1]), "+f"((d)[2]), "+f"((d)[3]) \
        : "r"((a)[0]), "r"((a)[1]), "r"((a)[2]), "r"((a)[3]), "r"(b0), "r"(b1))

__device__ __forceinline__ void lda(uint32_t* a, const char* s, int base_r, int lr, int lc2, int k16) {
    int b = (base_r + lr) * RS + k16 * 32 + lc2;
    a[0] = *(const uint32_t*)(s + b);
    a[1] = *(const uint32_t*)(s + b + 8 * RS);
    a[2] = *(const uint32_t*)(s + b + 16);
    a[3] = *(const uint32_t*)(s + b + 8 * RS + 16);
}
__device__ __forceinline__ void ldb(uint32_t* b, const char* s, int base_n, int lr, int lc2, int k16) {
    int o = (base_n + lr) * RS + k16 * 32 + lc2;
    b[0] = *(const uint32_t*)(s + o);
    b[1] = *(const uint32_t*)(s + o + 16);
}

__device__ __forceinline__ uint32_t pack2(float v0, float v1, uint32_t& lo_out) {
    __nv_bfloat16 h0 = __float2bfloat16(v0);
    __nv_bfloat16 h1 = __float2bfloat16(v1);
    __nv_bfloat16 l0 = __float2bfloat16(v0 - __bfloat162float(h0));
    __nv_bfloat16 l1 = __float2bfloat16(v1 - __bfloat162float(h1));
    lo_out = (uint32_t)__bfloat16_as_ushort(l0) | ((uint32_t)__bfloat16_as_ushort(l1) << 16);
    return (uint32_t)__bfloat16_as_ushort(h0) | ((uint32_t)__bfloat16_as_ushort(h1) << 16);
}

// ---------------- conversion: fp32 -> (hi,lo) bf16 ----------------
__global__ void __launch_bounds__(256)
convert_kernel(const float* __restrict__ src,
               __nv_bfloat16* __restrict__ hi,
               __nv_bfloat16* __restrict__ lo, size_t n)
{
    size_t i = ((size_t)blockIdx.x * 256 + threadIdx.x) * 4;
    if (i >= n) return;
    float4 v = *(const float4*)(src + i);
    uint32_t l01, l23;
    uint32_t h01 = pack2(v.x, v.y, l01);
    uint32_t h23 = pack2(v.z, v.w, l23);
    *(uint2*)(hi + i) = make_uint2(h01, h23);
    *(uint2*)(lo + i) = make_uint2(l01, l23);
}

// ---------------- routing: warp-per-expert, ballot compaction ----------------
__global__ void route_kernel(const unsigned* __restrict__ idx_raw,
                             const float* __restrict__ wts)
{
    __shared__ int s_flag;
    __shared__ int s_cnt[E_NUM];
    __shared__ int s_off[E_NUM + 1];
    const int tid = threadIdx.x, wid = tid >> 5, lane = tid & 31;

    if (tid == 0) s_flag = 0;
    __syncthreads();
    unsigned acc = 0;
    for (int i = 1 + 2 * tid; i < T_NUM * TOPK; i += 512) acc |= idx_raw[i];
    if (acc) atomicOr(&s_flag, 1);
    __syncthreads();
    const int is64 = (s_flag == 0) ? 1 : 0;

    const int e = wid;
    int c = 0;
    for (int base = 0; base < T_NUM; base += 32) {
        int t = base + lane;
        int e0 = is64 ? (int)idx_raw[4 * t]     : (int)idx_raw[2 * t];
        int e1 = is64 ? (int)idx_raw[4 * t + 2] : (int)idx_raw[2 * t + 1];
        c += (e0 == e || e1 == e) ? 1 : 0;
    }
#pragma unroll
    for (int o = 16; o; o >>= 1) c += __shfl_down_sync(0xffffffffu, c, o);
    if (lane == 0) s_cnt[e] = c;
    __syncthreads();
    if (tid == 0) {
        int o = 0;
        for (int i = 0; i < E_NUM; i++) { s_off[i] = o; g_off[i] = o; g_cnt[i] = s_cnt[i]; o += s_cnt[i]; }
        s_off[E_NUM] = o; g_off[E_NUM] = o;
    }
    __syncthreads();
    int p = s_off[e];
    for (int base = 0; base < T_NUM; base += 32) {
        int t = base + lane;
        int e0 = is64 ? (int)idx_raw[4 * t]     : (int)idx_raw[2 * t];
        int e1 = is64 ? (int)idx_raw[4 * t + 2] : (int)idx_raw[2 * t + 1];
        bool m = (e0 == e || e1 == e);
        float w = (e0 == e ? wts[2 * t] : 0.0f) + (e1 == e ? wts[2 * t + 1] : 0.0f);
        unsigned msk = __ballot_sync(0xffffffffu, m);
        int pos = p + __popc(msk & ((1u << lane) - 1u));
        if (m) { g_tok[pos] = t; g_wgt[pos] = w; }
        p += __popc(msk);
    }
}

// ---------------- GEMM1 ----------------
// SMEM: s_tok [0,512), stages at 512. Stage = 6 tiles x 10240B:
// AH 0, AL 10240, GH 20480, GL 30720, UH 40960, UL 51200
#define ST1 (6 * TM * RS)                 // 61440
#define G1_SMEM (512 + NSTAGE * ST1)      // 184832

__global__ void __launch_bounds__(NTHREADS, 1)
gemm1_kernel()
{
    const int e = blockIdx.z;
    const int cnt = g_cnt[e];
    const int rowBase = blockIdx.y * TM;
    if (rowBase >= cnt) return;
    const int off = g_off[e];
    const int n0 = blockIdx.x * TN;

    extern __shared__ char smem[];
    int* s_tok = (int*)smem;
    const uint32_t sb = smem_u32(smem);

    const int tid = threadIdx.x, wid = tid >> 5, lane = tid & 31;
    const int wm = wid >> 2, wn = wid & 3;
    const int lr = lane >> 2, lc2 = (lane & 3) << 2;

    if (tid < TM) { int r = rowBase + tid; s_tok[tid] = (r < cnt) ? g_tok[off + r] : -1; }
    __syncthreads();

    // staging: thread -> (row = tid>>2, chunk = tid&3), one 16B chunk per tile
    const int srow = tid >> 2, sch = tid & 3;
    const int selem = sch * 8;
    const uint32_t sdst = sb + 512 + (uint32_t)(srow * RS + sch * 16);
    const int stok = s_tok[srow];
    const int asz = (stok >= 0) ? 16 : 0;
    const size_t arow = (size_t)(stok >= 0 ? stok : 0) * H_DIM + selem;
    const size_t wrow = ((size_t)e * I_DIM + n0 + srow) * H_DIM + selem;
    const __nv_bfloat16* axh = g_xh + arow;
    const __nv_bfloat16* axl = g_xl + arow;
    const __nv_bfloat16* agh = g_gh + wrow;
    const __nv_bfloat16* agl = g_gl + wrow;
    const __nv_bfloat16* auh = g_uh + wrow;
    const __nv_bfloat16* aul = g_ul + wrow;

    float accG[2][4][4], accU[2][4][4];
#pragma unroll
    for (int i = 0; i < 2; i++)
#pragma unroll
        for (int j = 0; j < 4; j++)
#pragma unroll
            for (int k = 0; k < 4; k++) { accG[i][j][k] = 0.0f; accU[i][j][k] = 0.0f; }

    const int KB = H_DIM / TK;   // 64

#define G1_ISSUE(kb, st) do { \
        uint32_t b_ = sdst + (uint32_t)(st) * ST1; \
        int kk_ = (kb) * TK; \
        cpa16(b_ +     0, axh + kk_, asz); \
        cpa16(b_ + 10240, axl + kk_, asz); \
        cpa16(b_ + 20480, agh + kk_, 16); \
        cpa16(b_ + 30720, agl + kk_, 16); \
        cpa16(b_ + 40960, auh + kk_, 16); \
        cpa16(b_ + 51200, aul + kk_, 16); \
        CP_COMMIT(); \
    } while (0)

    G1_ISSUE(0, 0);
    G1_ISSUE(1, 1);

    for (int kb = 0; kb < KB; kb++) {
        if (kb + 1 < KB) { CP_WAIT1(); } else { CP_WAIT0(); }
        __syncthreads();
        if (kb + 2 < KB) G1_ISSUE(kb + 2, (kb + 2) % NSTAGE);

        const char* stg = smem + 512 + (kb % NSTAGE) * ST1;
        const char* sAH = stg;          const char* sAL = stg + 10240;
        const char* sGH = stg + 20480;  const char* sGL = stg + 30720;
        const char* sUH = stg + 40960;  const char* sUL = stg + 51200;

#pragma unroll
        for (int k16 = 0; k16 < 2; k16++) {
            uint32_t aH[2][4], aL[2][4];
#pragma unroll
            for (int mt = 0; mt < 2; mt++) {
                lda(aH[mt], sAH, wm * 32 + mt * 16, lr, lc2, k16);
                lda(aL[mt], sAL, wm * 32 + mt * 16, lr, lc2, k16);
            }
#pragma unroll
            for (int nt = 0; nt < 4; nt++) {
                uint32_t bgH[2], bgL[2], buH[2], buL[2];
                ldb(bgH, sGH, wn * 32 + nt * 8, lr, lc2, k16);
                ldb(bgL, sGL, wn * 32 + nt * 8, lr, lc2, k16);
                ldb(buH, sUH, wn * 32 + nt * 8, lr, lc2, k16);
                ldb(buL, sUL, wn * 32 + nt * 8, lr, lc2, k16);
#pragma unroll
                for (int mt = 0; mt < 2; mt++) {
                    MMA(accG[mt][nt], aH[mt], bgH[0], bgH[1]);
                    MMA(accG[mt][nt], aH[mt], bgL[0], bgL[1]);
                    MMA(accG[mt][nt], aL[mt], bgH[0], bgH[1]);
                    MMA(accU[mt][nt], aH[mt], buH[0], buH[1]);
                    MMA(accU[mt][nt], aH[mt], buL[0], buL[1]);
                    MMA(accU[mt][nt], aL[mt], buH[0], buH[1]);
                }
            }
        }
    }
#undef G1_ISSUE

    // epilogue: silu(g)*u, split to inter hi/lo
#pragma unroll
    for (int mt = 0; mt < 2; mt++) {
#pragma unroll
        for (int half = 0; half < 2; half++) {
            int rloc = wm * 32 + mt * 16 + lr + half * 8;
            int r = rowBase + rloc;
            if (r >= cnt) continue;
            size_t base = (size_t)(off + r) * I_DIM + n0 + wn * 32 + (lc2 >> 1);
#pragma unroll
            for (int nt = 0; nt < 4; nt++) {
                float g0 = accG[mt][nt][half * 2 + 0], u0 = accU[mt][nt][half * 2 + 0];
                float g1 = accG[mt][nt][half * 2 + 1], u1 = accU[mt][nt][half * 2 + 1];
                float v0 = (g0 / (1.0f + __expf(-g0))) * u0;
                float v1 = (g1 / (1.0f + __expf(-g1))) * u1;
                uint32_t lo;
                uint32_t hi = pack2(v0, v1, lo);
                *(uint32_t*)(g_ih + base + nt * 8) = hi;
                *(uint32_t*)(g_il + base + nt * 8) = lo;
            }
        }
    }
}

// ---------------- GEMM2 ----------------
// SMEM: s_tok [0,512), s_wgt [512,1024), stages at 1024. Stage = 4 tiles:
// AH 0, AL 10240, BH 20480, BL 30720
#define ST2 (4 * TM * RS)                 // 40960
#define G2_SMEM (1024 + NSTAGE * ST2)     // 123904

__global__ void __launch_bounds__(NTHREADS, 1)
gemm2_kernel(float* __restrict__ out)
{
    const int e = blockIdx.z;
    const int cnt = g_cnt[e];
    const int rowBase = blockIdx.y * TM;
    if (rowBase >= cnt) return;
    const int off = g_off[e];
    const int n0 = blockIdx.x * TN;

    extern __shared__ char smem[];
    int*   s_tok = (int*)smem;
    float* s_wgt = (float*)(smem + 512);
    const uint32_t sb = smem_u32(smem);

    const int tid = threadIdx.x, wid = tid >> 5, lane = tid & 31;
    const int wm = wid >> 2, wn = wid & 3;
    const int lr = lane >> 2, lc2 = (lane & 3) << 2;

    if (tid < TM) {
        int r = rowBase + tid;
        s_tok[tid] = (r < cnt) ? g_tok[off + r] : -1;
        s_wgt[tid] = (r < cnt) ? g_wgt[off + r] : 0.0f;
    }
    __syncthreads();

    const int srow = tid >> 2, sch = tid & 3;
    const int selem = sch * 8;
    const uint32_t sdst = sb + 1024 + (uint32_t)(srow * RS + sch * 16);
    const int valid = (rowBase + srow < cnt);
    const int asz = valid ? 16 : 0;
    const size_t arow = (size_t)(off + (valid ? rowBase + srow : 0)) * I_DIM + selem;
    const size_t brow = ((size_t)e * H_DIM + n0 + srow) * I_DIM + selem;
    const __nv_bfloat16* aih = g_ih + arow;
    const __nv_bfloat16* ail = g_il + arow;
    const __nv_bfloat16* adh = g_dh + brow;
    const __nv_bfloat16* adl = g_dl + brow;

    float acc[2][4][4];
#pragma unroll
    for (int i = 0; i < 2; i++)
#pragma unroll
        for (int j = 0; j < 4; j++)
#pragma unroll
            for (int k = 0; k < 4; k++) acc[i][j][k] = 0.0f;

    const int KB = I_DIM / TK;   // 128

#define G2_ISSUE(kb, st) do { \
        uint32_t b_ = sdst + (uint32_t)(st) * ST2; \
        int kk_ = (kb) * TK; \
        cpa16(b_ +     0, aih + kk_, asz); \
        cpa16(b_ + 10240, ail + kk_, asz); \
        cpa16(b_ + 20480, adh + kk_, 16); \
        cpa16(b_ + 30720, adl + kk_, 16); \
        CP_COMMIT(); \
    } while (0)

    G2_ISSUE(0, 0);
    G2_ISSUE(1, 1);

    for (int kb = 0; kb < KB; kb++) {
        if (kb + 1 < KB) { CP_WAIT1(); } else { CP_WAIT0(); }
        __syncthreads();
        if (kb + 2 < KB) G2_ISSUE(kb + 2, (kb + 2) % NSTAGE);

        const char* stg = smem + 1024 + (kb % NSTAGE) * ST2;
        const char* sAH = stg;          const char* sAL = stg + 10240;
        const char* sBH = stg + 20480;  const char* sBL = stg + 30720;

#pragma unroll
        for (int k16 = 0; k16 < 2; k16++) {
            uint32_t aH[2][4], aL[2][4];
#pragma unroll
            for (int mt = 0; mt < 2; mt++) {
                lda(aH[mt], sAH, wm * 32 + mt * 16, lr, lc2, k16);
                lda(aL[mt], sAL, wm * 32 + mt * 16, lr, lc2, k16);
            }
#pragma unroll
            for (int nt = 0; nt < 4; nt++) {
                uint32_t bH[2], bL[2];
                ldb(bH, sBH, wn * 32 + nt * 8, lr, lc2, k16);
                ldb(bL, sBL, wn * 32 + nt * 8, lr, lc2, k16);
#pragma unroll
                for (int mt = 0; mt < 2; mt++) {
                    MMA(acc[mt][nt], aH[mt], bH[0], bH[1]);
                    MMA(acc[mt][nt], aH[mt], bL[0], bL[1]);
                    MMA(acc[mt][nt], aL[mt], bH[0], bH[1]);
                }
            }
        }
    }
#undef G2_ISSUE

    // epilogue: weighted scatter-add
#pragma unroll
    for (int mt = 0; mt < 2; mt++) {
#pragma unroll
        for (int half = 0; half < 2; half++) {
            int rloc = wm * 32 + mt * 16 + lr + half * 8;
            int t = s_tok[rloc];
            if (t < 0) continue;
            float w = s_wgt[rloc];
            float* dst = out + (size_t)t * H_DIM + n0 + wn * 32 + (lc2 >> 1);
#pragma unroll
            for (int nt = 0; nt < 4; nt++) {
                atomicAdd(dst + nt * 8 + 0, w * acc[mt][nt][half * 2 + 0]);
                atomicAdd(dst + nt * 8 + 1, w * acc[mt][nt][half * 2 + 1]);
            }
        }
    }
}

// ---------------- launch ----------------
extern "C" void kernel_launch(void* const* d_in, const int* in_sizes, int n_in,
                              void* d_out, int out_size)
{
    const float*    x    = (const float*)d_in[0];
    const unsigned* idx  = (const unsigned*)d_in[1];
    const float*    wts  = (const float*)d_in[2];
    const float*    gate = (const float*)d_in[3];
    const float*    up   = (const float*)d_in[4];
    const float*    down = (const float*)d_in[5];
    float* out = (float*)d_out;

    static int attr_done = 0;
    if (!attr_done) {
        cudaFuncSetAttribute(gemm1_kernel, cudaFuncAttributeMaxDynamicSharedMemorySize, G1_SMEM);
        cudaFuncSetAttribute(gemm2_kernel, cudaFuncAttributeMaxDynamicSharedMemorySize, G2_SMEM);
        attr_done = 1;
    }

    cudaMemsetAsync(out, 0, (size_t)out_size * sizeof(float));
    route_kernel<<<1, 256>>>(idx, wts);

    __nv_bfloat16 *gh, *gl, *uh, *ul, *dh, *dl, *xh, *xl;
    cudaGetSymbolAddress((void**)&gh, g_gh); cudaGetSymbolAddress((void**)&gl, g_gl);
    cudaGetSymbolAddress((void**)&uh, g_uh); cudaGetSymbolAddress((void**)&ul, g_ul);
    cudaGetSymbolAddress((void**)&dh, g_dh); cudaGetSymbolAddress((void**)&dl, g_dl);
    cudaGetSymbolAddress((void**)&xh, g_xh); cudaGetSymbolAddress((void**)&xl, g_xl);

    const size_t nw = NW;                         // 67,108,864
    const size_t nx = (size_t)T_NUM * H_DIM;      // 8,388,608
    convert_kernel<<<(unsigned)(nw / 1024), 256>>>(gate, gh, gl, nw);
    convert_kernel<<<(unsigned)(nw / 1024), 256>>>(up,   uh, ul, nw);
    convert_kernel<<<(unsigned)(nw / 1024), 256>>>(down, dh, dl, nw);
    convert_kernel<<<(unsigned)(nx / 1024), 256>>>(x,    xh, xl, nx);

    gemm1_kernel<<<dim3(I_DIM / TN, T_NUM / TM, E_NUM), NTHREADS, G1_SMEM>>>();
    gemm2_kernel<<<dim3(H_DIM / TN, T_NUM / TM, E_NUM), NTHREADS, G2_SMEM>>>(out);
}

// round 6
// speedup vs baseline: 2.9319x; 1.1001x over previous
#include <cuda_runtime.h>
#include <cuda_bf16.h>
#include <stdint.h>

// ---------------- problem constants ----------------
#define H_DIM 2048
#define I_DIM 4096
#define E_NUM 8
#define T_NUM 4096   // B*S
#define TOPK  2

#define TM 128
#define TN 128
#define TK 32
#define NTHREADS 512
#define RS 80        // SMEM row stride bytes (32 bf16 = 64B + 16B pad)
#define NSTAGE 3

// ---------------- scratch (__device__ globals: allocation-free) ----------------
__device__ int   g_tok[T_NUM * TOPK];
__device__ float g_wgt[T_NUM * TOPK];
__device__ int   g_cnt[E_NUM];
__device__ int   g_off[E_NUM + 1];

#define NW ((size_t)E_NUM * I_DIM * H_DIM)
__device__ __nv_bfloat16 g_xh[(size_t)T_NUM * H_DIM];
__device__ __nv_bfloat16 g_xl[(size_t)T_NUM * H_DIM];
__device__ __nv_bfloat16 g_gh[NW];
__device__ __nv_bfloat16 g_gl[NW];
__device__ __nv_bfloat16 g_uh[NW];
__device__ __nv_bfloat16 g_ul[NW];
__device__ __nv_bfloat16 g_dh[NW];
__device__ __nv_bfloat16 g_dl[NW];
__device__ __nv_bfloat16 g_ih[(size_t)T_NUM * TOPK * I_DIM];
__device__ __nv_bfloat16 g_il[(size_t)T_NUM * TOPK * I_DIM];

// ---------------- helpers ----------------
__device__ __forceinline__ void cpa16(uint32_t dst, const void* src, int srcsz) {
    asm volatile("cp.async.cg.shared.global [%0], [%1], 16, %2;"
                 :: "r"(dst), "l"(src), "r"(srcsz) : "memory");
}
#define CP_COMMIT() asm volatile("cp.async.commit_group;" ::: "memory")
#define CP_WAIT1()  asm volatile("cp.async.wait_group 1;" ::: "memory")
#define CP_WAIT0()  asm volatile("cp.async.wait_group 0;" ::: "memory")

__device__ __forceinline__ uint32_t smem_u32(const void* p) {
    uint32_t a;
    asm("{ .reg .u64 t; cvta.to.shared.u64 t, %1; cvt.u32.u64 %0, t; }" : "=r"(a) : "l"(p));
    return a;
}

#define MMA(d, a, b0, b1) \
    asm volatile("mma.sync.aligned.m16n8k16.row.col.f32.bf16.bf16.f32 " \
        "{%0,%1,%2,%3}, {%4,%5,%6,%7}, {%8,%9}, {%0,%1,%2,%3};" \
        : "+f"((d)[0]), "+f"((d)[1]), "+f"((d)[2]), "+f"((d)[3]) \
        : "r"((a)[0]), "r"((a)[1]), "r"((a)[2]), "r"((a)[3]), "r"(b0), "r"(b1))

#define LDSM4(R, addr) \
    asm volatile("ldmatrix.sync.aligned.m8n8.x4.shared.b16 {%0,%1,%2,%3}, [%4];" \
        : "=r"((R)[0]), "=r"((R)[1]), "=r"((R)[2]), "=r"((R)[3]) : "r"(addr))

__device__ __forceinline__ uint32_t pack2(float v0, float v1, uint32_t& lo_out) {
    __nv_bfloat16 h0 = __float2bfloat16(v0);
    __nv_bfloat16 h1 = __float2bfloat16(v1);
    __nv_bfloat16 l0 = __float2bfloat16(v0 - __bfloat162float(h0));
    __nv_bfloat16 l1 = __float2bfloat16(v1 - __bfloat162float(h1));
    lo_out = (uint32_t)__bfloat16_as_ushort(l0) | ((uint32_t)__bfloat16_as_ushort(l1) << 16);
    return (uint32_t)__bfloat16_as_ushort(h0) | ((uint32_t)__bfloat16_as_ushort(h1) << 16);
}

// ---------------- conversion: fp32 -> (hi,lo) bf16 ----------------
__global__ void __launch_bounds__(256)
convert_kernel(const float* __restrict__ src,
               __nv_bfloat16* __restrict__ hi,
               __nv_bfloat16* __restrict__ lo, size_t n)
{
    size_t i = ((size_t)blockIdx.x * 256 + threadIdx.x) * 4;
    if (i >= n) return;
    float4 v = *(const float4*)(src + i);
    uint32_t l01, l23;
    uint32_t h01 = pack2(v.x, v.y, l01);
    uint32_t h23 = pack2(v.z, v.w, l23);
    *(uint2*)(hi + i) = make_uint2(h01, h23);
    *(uint2*)(lo + i) = make_uint2(l01, l23);
}

// ---------------- routing ----------------
__global__ void route_kernel(const unsigned* __restrict__ idx_raw,
                             const float* __restrict__ wts)
{
    __shared__ int s_flag;
    __shared__ int s_cnt[E_NUM];
    __shared__ int s_off[E_NUM + 1];
    const int tid = threadIdx.x, wid = tid >> 5, lane = tid & 31;

    if (tid == 0) s_flag = 0;
    __syncthreads();
    unsigned acc = 0;
    for (int i = 1 + 2 * tid; i < T_NUM * TOPK; i += 512) acc |= idx_raw[i];
    if (acc) atomicOr(&s_flag, 1);
    __syncthreads();
    const int is64 = (s_flag == 0) ? 1 : 0;

    const int e = wid;
    int c = 0;
    for (int base = 0; base < T_NUM; base += 32) {
        int t = base + lane;
        int e0 = is64 ? (int)idx_raw[4 * t]     : (int)idx_raw[2 * t];
        int e1 = is64 ? (int)idx_raw[4 * t + 2] : (int)idx_raw[2 * t + 1];
        c += (e0 == e || e1 == e) ? 1 : 0;
    }
#pragma unroll
    for (int o = 16; o; o >>= 1) c += __shfl_down_sync(0xffffffffu, c, o);
    if (lane == 0) s_cnt[e] = c;
    __syncthreads();
    if (tid == 0) {
        int o = 0;
        for (int i = 0; i < E_NUM; i++) { s_off[i] = o; g_off[i] = o; g_cnt[i] = s_cnt[i]; o += s_cnt[i]; }
        s_off[E_NUM] = o; g_off[E_NUM] = o;
    }
    __syncthreads();
    int p = s_off[e];
    for (int base = 0; base < T_NUM; base += 32) {
        int t = base + lane;
        int e0 = is64 ? (int)idx_raw[4 * t]     : (int)idx_raw[2 * t];
        int e1 = is64 ? (int)idx_raw[4 * t + 2] : (int)idx_raw[2 * t + 1];
        bool m = (e0 == e || e1 == e);
        float w = (e0 == e ? wts[2 * t] : 0.0f) + (e1 == e ? wts[2 * t + 1] : 0.0f);
        unsigned msk = __ballot_sync(0xffffffffu, m);
        int pos = p + __popc(msk & ((1u << lane) - 1u));
        if (m) { g_tok[pos] = t; g_wgt[pos] = w; }
        p += __popc(msk);
    }
}

// ---------------- GEMM1 ----------------
// stage tiles: AH 0, AL 10240, GH 20480, GL 30720, UH 40960, UL 51200
#define ST1 (6 * TM * RS)                 // 61440
#define G1_SMEM (512 + NSTAGE * ST1)      // 184832

__global__ void __launch_bounds__(NTHREADS, 1)
gemm1_kernel()
{
    const int e = blockIdx.z;
    const int cnt = g_cnt[e];
    const int rowBase = blockIdx.y * TM;
    if (rowBase >= cnt) return;
    const int off = g_off[e];
    const int n0 = blockIdx.x * TN;

    extern __shared__ char smem[];
    int* s_tok = (int*)smem;
    const uint32_t sb = smem_u32(smem);

    const int tid = threadIdx.x, wid = tid >> 5, lane = tid & 31;
    const int wm = wid >> 2, wn = wid & 3;
    const int lr = lane >> 2, lc2 = (lane & 3) << 2;
    const int lg = lane >> 3, l7 = lane & 7;

    if (tid < TM) { int r = rowBase + tid; s_tok[tid] = (r < cnt) ? g_tok[off + r] : -1; }
    __syncthreads();

    // cp.async staging
    const int srow = tid >> 2, sch = tid & 3;
    const int selem = sch * 8;
    const uint32_t sdst = sb + 512 + (uint32_t)(srow * RS + sch * 16);
    const int stok = s_tok[srow];
    const int asz = (stok >= 0) ? 16 : 0;
    const size_t arow = (size_t)(stok >= 0 ? stok : 0) * H_DIM + selem;
    const size_t wrow = ((size_t)e * I_DIM + n0 + srow) * H_DIM + selem;
    const __nv_bfloat16* axh = g_xh + arow;
    const __nv_bfloat16* axl = g_xl + arow;
    const __nv_bfloat16* agh = g_gh + wrow;
    const __nv_bfloat16* agl = g_gl + wrow;
    const __nv_bfloat16* auh = g_uh + wrow;
    const __nv_bfloat16* aul = g_ul + wrow;

    // ldmatrix lane offsets
    // A (m-major): row = wm*32 + (lg&1)*8 + l7 (+mt*16), kbyte = (lg>>1)*16 (+k16*32)
    const uint32_t aoff = (uint32_t)((wm * 32 + ((lg & 1) << 3) + l7) * RS + ((lg >> 1) << 4));
    // B (n-major): row = wn*32 + (lg>>1)*8 + l7 (+nt2*16), kbyte = (lg&1)*16 (+k16*32)
    const uint32_t boff = (uint32_t)((wn * 32 + ((lg >> 1) << 3) + l7) * RS + ((lg & 1) << 4));

    float accG[2][4][4], accU[2][4][4];
#pragma unroll
    for (int i = 0; i < 2; i++)
#pragma unroll
        for (int j = 0; j < 4; j++)
#pragma unroll
            for (int k = 0; k < 4; k++) { accG[i][j][k] = 0.0f; accU[i][j][k] = 0.0f; }

    const int KB = H_DIM / TK;

#define G1_ISSUE(kb, st) do { \
        uint32_t b_ = sdst + (uint32_t)(st) * ST1; \
        int kk_ = (kb) * TK; \
        cpa16(b_ +     0, axh + kk_, asz); \
        cpa16(b_ + 10240, axl + kk_, asz); \
        cpa16(b_ + 20480, agh + kk_, 16); \
        cpa16(b_ + 30720, agl + kk_, 16); \
        cpa16(b_ + 40960, auh + kk_, 16); \
        cpa16(b_ + 51200, aul + kk_, 16); \
        CP_COMMIT(); \
    } while (0)

    G1_ISSUE(0, 0);
    G1_ISSUE(1, 1);

    for (int kb = 0; kb < KB; kb++) {
        if (kb + 1 < KB) { CP_WAIT1(); } else { CP_WAIT0(); }
        __syncthreads();
        if (kb + 2 < KB) G1_ISSUE(kb + 2, (kb + 2) % NSTAGE);

        const uint32_t s0 = sb + 512 + (uint32_t)((kb % NSTAGE) * ST1);
        const uint32_t sA = s0 + aoff;
        const uint32_t sB = s0 + boff;

#pragma unroll
        for (int k16 = 0; k16 < 2; k16++) {
            const uint32_t ka = (uint32_t)(k16 * 32);
            uint32_t aH[2][4], aL[2][4];
            LDSM4(aH[0], sA + ka);
            LDSM4(aH[1], sA + 16 * RS + ka);
            LDSM4(aL[0], sA + 10240 + ka);
            LDSM4(aL[1], sA + 10240 + 16 * RS + ka);
#pragma unroll
            for (int nt2 = 0; nt2 < 2; nt2++) {
                const uint32_t bn = sB + (uint32_t)(nt2 * 16 * RS) + ka;
                uint32_t b[4];
                // gate hi: pairs with aH and aL
                LDSM4(b, bn + 20480);
                MMA(accG[0][nt2 * 2 + 0], aH[0], b[0], b[1]);
                MMA(accG[0][nt2 * 2 + 1], aH[0], b[2], b[3]);
                MMA(accG[1][nt2 * 2 + 0], aH[1], b[0], b[1]);
                MMA(accG[1][nt2 * 2 + 1], aH[1], b[2], b[3]);
                MMA(accG[0][nt2 * 2 + 0], aL[0], b[0], b[1]);
                MMA(accG[0][nt2 * 2 + 1], aL[0], b[2], b[3]);
                MMA(accG[1][nt2 * 2 + 0], aL[1], b[0], b[1]);
                MMA(accG[1][nt2 * 2 + 1], aL[1], b[2], b[3]);
                // gate lo: pairs with aH only
                LDSM4(b, bn + 30720);
                MMA(accG[0][nt2 * 2 + 0], aH[0], b[0], b[1]);
                MMA(accG[0][nt2 * 2 + 1], aH[0], b[2], b[3]);
                MMA(accG[1][nt2 * 2 + 0], aH[1], b[0], b[1]);
                MMA(accG[1][nt2 * 2 + 1], aH[1], b[2], b[3]);
                // up hi
                LDSM4(b, bn + 40960);
                MMA(accU[0][nt2 * 2 + 0], aH[0], b[0], b[1]);
                MMA(accU[0][nt2 * 2 + 1], aH[0], b[2], b[3]);
                MMA(accU[1][nt2 * 2 + 0], aH[1], b[0], b[1]);
                MMA(accU[1][nt2 * 2 + 1], aH[1], b[2], b[3]);
                MMA(accU[0][nt2 * 2 + 0], aL[0], b[0], b[1]);
                MMA(accU[0][nt2 * 2 + 1], aL[0], b[2], b[3]);
                MMA(accU[1][nt2 * 2 + 0], aL[1], b[0], b[1]);
                MMA(accU[1][nt2 * 2 + 1], aL[1], b[2], b[3]);
                // up lo
                LDSM4(b, bn + 51200);
                MMA(accU[0][nt2 * 2 + 0], aH[0], b[0], b[1]);
                MMA(accU[0][nt2 * 2 + 1], aH[0], b[2], b[3]);
                MMA(accU[1][nt2 * 2 + 0], aH[1], b[0], b[1]);
                MMA(accU[1][nt2 * 2 + 1], aH[1], b[2], b[3]);
            }
        }
    }
#undef G1_ISSUE

    // epilogue: silu(g)*u -> inter hi/lo
#pragma unroll
    for (int mt = 0; mt < 2; mt++) {
#pragma unroll
        for (int half = 0; half < 2; half++) {
            int rloc = wm * 32 + mt * 16 + lr + half * 8;
            int r = rowBase + rloc;
            if (r >= cnt) continue;
            size_t base = (size_t)(off + r) * I_DIM + n0 + wn * 32 + (lc2 >> 1);
#pragma unroll
            for (int nt = 0; nt < 4; nt++) {
                float g0 = accG[mt][nt][half * 2 + 0], u0 = accU[mt][nt][half * 2 + 0];
                float g1 = accG[mt][nt][half * 2 + 1], u1 = accU[mt][nt][half * 2 + 1];
                float v0 = (g0 / (1.0f + __expf(-g0))) * u0;
                float v1 = (g1 / (1.0f + __expf(-g1))) * u1;
                uint32_t lo;
                uint32_t hi = pack2(v0, v1, lo);
                *(uint32_t*)(g_ih + base + nt * 8) = hi;
                *(uint32_t*)(g_il + base + nt * 8) = lo;
            }
        }
    }
}

// ---------------- GEMM2 ----------------
// stage tiles: AH 0, AL 10240, BH 20480, BL 30720
#define ST2 (4 * TM * RS)                 // 40960
#define G2_SMEM (1024 + NSTAGE * ST2)     // 123904

__global__ void __launch_bounds__(NTHREADS, 1)
gemm2_kernel(float* __restrict__ out)
{
    const int e = blockIdx.z;
    const int cnt = g_cnt[e];
    const int rowBase = blockIdx.y * TM;
    if (rowBase >= cnt) return;
    const int off = g_off[e];
    const int n0 = blockIdx.x * TN;

    extern __shared__ char smem[];
    int*   s_tok = (int*)smem;
    float* s_wgt = (float*)(smem + 512);
    const uint32_t sb = smem_u32(smem);

    const int tid = threadIdx.x, wid = tid >> 5, lane = tid & 31;
    const int wm = wid >> 2, wn = wid & 3;
    const int lr = lane >> 2, lc2 = (lane & 3) << 2;
    const int lg = lane >> 3, l7 = lane & 7;

    if (tid < TM) {
        int r = rowBase + tid;
        s_tok[tid] = (r < cnt) ? g_tok[off + r] : -1;
        s_wgt[tid] = (r < cnt) ? g_wgt[off + r] : 0.0f;
    }
    __syncthreads();

    const int srow = tid >> 2, sch = tid & 3;
    const int selem = sch * 8;
    const uint32_t sdst = sb + 1024 + (uint32_t)(srow * RS + sch * 16);
    const int valid = (rowBase + srow < cnt);
    const int asz = valid ? 16 : 0;
    const size_t arow = (size_t)(off + (valid ? rowBase + srow : 0)) * I_DIM + selem;
    const size_t brow = ((size_t)e * H_DIM + n0 + srow) * I_DIM + selem;
    const __nv_bfloat16* aih = g_ih + arow;
    const __nv_bfloat16* ail = g_il + arow;
    const __nv_bfloat16* adh = g_dh + brow;
    const __nv_bfloat16* adl = g_dl + brow;

    const uint32_t aoff = (uint32_t)((wm * 32 + ((lg & 1) << 3) + l7) * RS + ((lg >> 1) << 4));
    const uint32_t boff = (uint32_t)((wn * 32 + ((lg >> 1) << 3) + l7) * RS + ((lg & 1) << 4));

    float acc[2][4][4];
#pragma unroll
    for (int i = 0; i < 2; i++)
#pragma unroll
        for (int j = 0; j < 4; j++)
#pragma unroll
            for (int k = 0; k < 4; k++) acc[i][j][k] = 0.0f;

    const int KB = I_DIM / TK;

#define G2_ISSUE(kb, st) do { \
        uint32_t b_ = sdst + (uint32_t)(st) * ST2; \
        int kk_ = (kb) * TK; \
        cpa16(b_ +     0, aih + kk_, asz); \
        cpa16(b_ + 10240, ail + kk_, asz); \
        cpa16(b_ + 20480, adh + kk_, 16); \
        cpa16(b_ + 30720, adl + kk_, 16); \
        CP_COMMIT(); \
    } while (0)

    G2_ISSUE(0, 0);
    G2_ISSUE(1, 1);

    for (int kb = 0; kb < KB; kb++) {
        if (kb + 1 < KB) { CP_WAIT1(); } else { CP_WAIT0(); }
        __syncthreads();
        if (kb + 2 < KB) G2_ISSUE(kb + 2, (kb + 2) % NSTAGE);

        const uint32_t s0 = sb + 1024 + (uint32_t)((kb % NSTAGE) * ST2);
        const uint32_t sA = s0 + aoff;
        const uint32_t sB = s0 + boff;

#pragma unroll
        for (int k16 = 0; k16 < 2; k16++) {
            const uint32_t ka = (uint32_t)(k16 * 32);
            uint32_t aH[2][4], aL[2][4];
            LDSM4(aH[0], sA + ka);
            LDSM4(aH[1], sA + 16 * RS + ka);
            LDSM4(aL[0], sA + 10240 + ka);
            LDSM4(aL[1], sA + 10240 + 16 * RS + ka);
#pragma unroll
            for (int nt2 = 0; nt2 < 2; nt2++) {
                const uint32_t bn = sB + (uint32_t)(nt2 * 16 * RS) + ka;
                uint32_t b[4];
                // down hi: aH + aL
                LDSM4(b, bn + 20480);
                MMA(acc[0][nt2 * 2 + 0], aH[0], b[0], b[1]);
                MMA(acc[0][nt2 * 2 + 1], aH[0], b[2], b[3]);
                MMA(acc[1][nt2 * 2 + 0], aH[1], b[0], b[1]);
                MMA(acc[1][nt2 * 2 + 1], aH[1], b[2], b[3]);
                MMA(acc[0][nt2 * 2 + 0], aL[0], b[0], b[1]);
                MMA(acc[0][nt2 * 2 + 1], aL[0], b[2], b[3]);
                MMA(acc[1][nt2 * 2 + 0], aL[1], b[0], b[1]);
                MMA(acc[1][nt2 * 2 + 1], aL[1], b[2], b[3]);
                // down lo: aH only
                LDSM4(b, bn + 30720);
                MMA(acc[0][nt2 * 2 + 0], aH[0], b[0], b[1]);
                MMA(acc[0][nt2 * 2 + 1], aH[0], b[2], b[3]);
                MMA(acc[1][nt2 * 2 + 0], aH[1], b[0], b[1]);
                MMA(acc[1][nt2 * 2 + 1], aH[1], b[2], b[3]);
            }
        }
    }
#undef G2_ISSUE

    // epilogue: weighted scatter-add
#pragma unroll
    for (int mt = 0; mt < 2; mt++) {
#pragma unroll
        for (int half = 0; half < 2; half++) {
            int rloc = wm * 32 + mt * 16 + lr + half * 8;
            int t = s_tok[rloc];
            if (t < 0) continue;
            float w = s_wgt[rloc];
            float* dst = out + (size_t)t * H_DIM + n0 + wn * 32 + (lc2 >> 1);
#pragma unroll
            for (int nt = 0; nt < 4; nt++) {
                atomicAdd(dst + nt * 8 + 0, w * acc[mt][nt][half * 2 + 0]);
                atomicAdd(dst + nt * 8 + 1, w * acc[mt][nt][half * 2 + 1]);
            }
        }
    }
}

// ---------------- launch ----------------
extern "C" void kernel_launch(void* const* d_in, const int* in_sizes, int n_in,
                              void* d_out, int out_size)
{
    const float*    x    = (const float*)d_in[0];
    const unsigned* idx  = (const unsigned*)d_in[1];
    const float*    wts  = (const float*)d_in[2];
    const float*    gate = (const float*)d_in[3];
    const float*    up   = (const float*)d_in[4];
    const float*    down = (const float*)d_in[5];
    float* out = (float*)d_out;

    static int attr_done = 0;
    if (!attr_done) {
        cudaFuncSetAttribute(gemm1_kernel, cudaFuncAttributeMaxDynamicSharedMemorySize, G1_SMEM);
        cudaFuncSetAttribute(gemm2_kernel, cudaFuncAttributeMaxDynamicSharedMemorySize, G2_SMEM);
        attr_done = 1;
    }

    cudaMemsetAsync(out, 0, (size_t)out_size * sizeof(float));
    route_kernel<<<1, 256>>>(idx, wts);

    __nv_bfloat16 *gh, *gl, *uh, *ul, *dh, *dl, *xh, *xl;
    cudaGetSymbolAddress((void**)&gh, g_gh); cudaGetSymbolAddress((void**)&gl, g_gl);
    cudaGetSymbolAddress((void**)&uh, g_uh); cudaGetSymbolAddress((void**)&ul, g_ul);
    cudaGetSymbolAddress((void**)&dh, g_dh); cudaGetSymbolAddress((void**)&dl, g_dl);
    cudaGetSymbolAddress((void**)&xh, g_xh); cudaGetSymbolAddress((void**)&xl, g_xl);

    const size_t nw = NW;
    const size_t nx = (size_t)T_NUM * H_DIM;
    convert_kernel<<<(unsigned)(nw / 1024), 256>>>(gate, gh, gl, nw);
    convert_kernel<<<(unsigned)(nw / 1024), 256>>>(up,   uh, ul, nw);
    convert_kernel<<<(unsigned)(nw / 1024), 256>>>(down, dh, dl, nw);
    convert_kernel<<<(unsigned)(nx / 1024), 256>>>(x,    xh, xl, nx);

    gemm1_kernel<<<dim3(I_DIM / TN, T_NUM / TM, E_NUM), NTHREADS, G1_SMEM>>>();
    gemm2_kernel<<<dim3(H_DIM / TN, T_NUM / TM, E_NUM), NTHREADS, G2_SMEM>>>(out);
}

// round 7
// speedup vs baseline: 2.9623x; 1.0104x over previous
#include <cuda_runtime.h>
#include <cuda_bf16.h>
#include <stdint.h>

// ---------------- problem constants ----------------
#define H_DIM 2048
#define I_DIM 4096
#define E_NUM 8
#define T_NUM 4096   // B*S
#define TOPK  2

#define TM 128
#define TN 128
#define TK 32
#define NTHREADS 512
#define RS 80        // SMEM row stride bytes (32 bf16 = 64B + 16B pad)
#define NSTAGE 3

// ---------------- scratch (__device__ globals: allocation-free) ----------------
__device__ int   g_tok[T_NUM * TOPK];
__device__ float g_wgt[T_NUM * TOPK];
__device__ int   g_cnt[E_NUM];
__device__ int   g_off[E_NUM + 1];

#define NW ((size_t)E_NUM * I_DIM * H_DIM)
__device__ __nv_bfloat16 g_xh[(size_t)T_NUM * H_DIM];
__device__ __nv_bfloat16 g_xl[(size_t)T_NUM * H_DIM];
__device__ __nv_bfloat16 g_gh[NW];
__device__ __nv_bfloat16 g_gl[NW];
__device__ __nv_bfloat16 g_uh[NW];
__device__ __nv_bfloat16 g_ul[NW];
__device__ __nv_bfloat16 g_dh[NW];
__device__ __nv_bfloat16 g_dl[NW];
__device__ __nv_bfloat16 g_ih[(size_t)T_NUM * TOPK * I_DIM];
__device__ __nv_bfloat16 g_il[(size_t)T_NUM * TOPK * I_DIM];

// ---------------- helpers ----------------
__device__ __forceinline__ void cpa16(uint32_t dst, const void* src, int srcsz) {
    asm volatile("cp.async.cg.shared.global [%0], [%1], 16, %2;"
                 :: "r"(dst), "l"(src), "r"(srcsz) : "memory");
}
#define CP_COMMIT() asm volatile("cp.async.commit_group;" ::: "memory")
#define CP_WAIT1()  asm volatile("cp.async.wait_group 1;" ::: "memory")
#define CP_WAIT0()  asm volatile("cp.async.wait_group 0;" ::: "memory")

__device__ __forceinline__ uint32_t smem_u32(const void* p) {
    uint32_t a;
    asm("{ .reg .u64 t; cvta.to.shared.u64 t, %1; cvt.u32.u64 %0, t; }" : "=r"(a) : "l"(p));
    return a;
}

#define MMA(d, a, b0, b1) \
    asm volatile("mma.sync.aligned.m16n8k16.row.col.f32.bf16.bf16.f32 " \
        "{%0,%1,%2,%3}, {%4,%5,%6,%7}, {%8,%9}, {%0,%1,%2,%3};" \
        : "+f"((d)[0]), "+f"((d)[1]), "+f"((d)[2]), "+f"((d)[3]) \
        : "r"((a)[0]), "r"((a)[1]), "r"((a)[2]), "r"((a)[3]), "r"(b0), "r"(b1))

#define LDSM4(R, addr) \
    asm volatile("ldmatrix.sync.aligned.m8n8.x4.shared.b16 {%0,%1,%2,%3}, [%4];" \
        : "=r"((R)[0]), "=r"((R)[1]), "=r"((R)[2]), "=r"((R)[3]) : "r"(addr))

__device__ __forceinline__ uint32_t pack2(float v0, float v1, uint32_t& lo_out) {
    __nv_bfloat16 h0 = __float2bfloat16(v0);
    __nv_bfloat16 h1 = __float2bfloat16(v1);
    __nv_bfloat16 l0 = __float2bfloat16(v0 - __bfloat162float(h0));
    __nv_bfloat16 l1 = __float2bfloat16(v1 - __bfloat162float(h1));
    lo_out = (uint32_t)__bfloat16_as_ushort(l0) | ((uint32_t)__bfloat16_as_ushort(l1) << 16);
    return (uint32_t)__bfloat16_as_ushort(h0) | ((uint32_t)__bfloat16_as_ushort(h1) << 16);
}

// ---------------- conversion: fp32 -> (hi,lo) bf16 ----------------
__global__ void __launch_bounds__(256)
convert_kernel(const float* __restrict__ src,
               __nv_bfloat16* __restrict__ hi,
               __nv_bfloat16* __restrict__ lo, size_t n)
{
    size_t i = ((size_t)blockIdx.x * 256 + threadIdx.x) * 4;
    if (i >= n) return;
    float4 v = *(const float4*)(src + i);
    uint32_t l01, l23;
    uint32_t h01 = pack2(v.x, v.y, l01);
    uint32_t h23 = pack2(v.z, v.w, l23);
    *(uint2*)(hi + i) = make_uint2(h01, h23);
    *(uint2*)(lo + i) = make_uint2(l01, l23);
}

// ---------------- routing ----------------
__global__ void route_kernel(const unsigned* __restrict__ idx_raw,
                             const float* __restrict__ wts)
{
    __shared__ int s_flag;
    __shared__ int s_cnt[E_NUM];
    __shared__ int s_off[E_NUM + 1];
    const int tid = threadIdx.x, wid = tid >> 5, lane = tid & 31;

    if (tid == 0) s_flag = 0;
    __syncthreads();
    unsigned acc = 0;
    for (int i = 1 + 2 * tid; i < T_NUM * TOPK; i += 512) acc |= idx_raw[i];
    if (acc) atomicOr(&s_flag, 1);
    __syncthreads();
    const int is64 = (s_flag == 0) ? 1 : 0;

    const int e = wid;
    int c = 0;
    for (int base = 0; base < T_NUM; base += 32) {
        int t = base + lane;
        int e0 = is64 ? (int)idx_raw[4 * t]     : (int)idx_raw[2 * t];
        int e1 = is64 ? (int)idx_raw[4 * t + 2] : (int)idx_raw[2 * t + 1];
        c += (e0 == e || e1 == e) ? 1 : 0;
    }
#pragma unroll
    for (int o = 16; o; o >>= 1) c += __shfl_down_sync(0xffffffffu, c, o);
    if (lane == 0) s_cnt[e] = c;
    __syncthreads();
    if (tid == 0) {
        int o = 0;
        for (int i = 0; i < E_NUM; i++) { s_off[i] = o; g_off[i] = o; g_cnt[i] = s_cnt[i]; o += s_cnt[i]; }
        s_off[E_NUM] = o; g_off[E_NUM] = o;
    }
    __syncthreads();
    int p = s_off[e];
    for (int base = 0; base < T_NUM; base += 32) {
        int t = base + lane;
        int e0 = is64 ? (int)idx_raw[4 * t]     : (int)idx_raw[2 * t];
        int e1 = is64 ? (int)idx_raw[4 * t + 2] : (int)idx_raw[2 * t + 1];
        bool m = (e0 == e || e1 == e);
        float w = (e0 == e ? wts[2 * t] : 0.0f) + (e1 == e ? wts[2 * t + 1] : 0.0f);
        unsigned msk = __ballot_sync(0xffffffffu, m);
        int pos = p + __popc(msk & ((1u << lane) - 1u));
        if (m) { g_tok[pos] = t; g_wgt[pos] = w; }
        p += __popc(msk);
    }
}

// ---------------- GEMM1 ----------------
// grid: x = row-tile (fastest; adjacent CTAs share the weight panel -> L2 reuse),
//       y = N-tile, z = expert
// stage tiles: AH 0, AL 10240, GH 20480, GL 30720, UH 40960, UL 51200
#define ST1 (6 * TM * RS)                 // 61440
#define G1_SMEM (512 + NSTAGE * ST1)      // 184832

__global__ void __launch_bounds__(NTHREADS, 1)
gemm1_kernel()
{
    const int e = blockIdx.z;
    const int cnt = g_cnt[e];
    const int rowBase = blockIdx.x * TM;
    if (rowBase >= cnt) return;
    const int off = g_off[e];
    const int n0 = blockIdx.y * TN;

    extern __shared__ char smem[];
    int* s_tok = (int*)smem;
    const uint32_t sb = smem_u32(smem);

    const int tid = threadIdx.x, wid = tid >> 5, lane = tid & 31;
    const int wm = wid >> 2, wn = wid & 3;
    const int lr = lane >> 2, lc2 = (lane & 3) << 2;
    const int lg = lane >> 3, l7 = lane & 7;

    if (tid < TM) { int r = rowBase + tid; s_tok[tid] = (r < cnt) ? g_tok[off + r] : -1; }
    __syncthreads();

    // cp.async staging
    const int srow = tid >> 2, sch = tid & 3;
    const int selem = sch * 8;
    const uint32_t sdst = sb + 512 + (uint32_t)(srow * RS + sch * 16);
    const int stok = s_tok[srow];
    const int asz = (stok >= 0) ? 16 : 0;
    const size_t arow = (size_t)(stok >= 0 ? stok : 0) * H_DIM + selem;
    const size_t wrow = ((size_t)e * I_DIM + n0 + srow) * H_DIM + selem;
    const __nv_bfloat16* axh = g_xh + arow;
    const __nv_bfloat16* axl = g_xl + arow;
    const __nv_bfloat16* agh = g_gh + wrow;
    const __nv_bfloat16* agl = g_gl + wrow;
    const __nv_bfloat16* auh = g_uh + wrow;
    const __nv_bfloat16* aul = g_ul + wrow;

    // ldmatrix lane offsets
    const uint32_t aoff = (uint32_t)((wm * 32 + ((lg & 1) << 3) + l7) * RS + ((lg >> 1) << 4));
    const uint32_t boff = (uint32_t)((wn * 32 + ((lg >> 1) << 3) + l7) * RS + ((lg & 1) << 4));

    float accG[2][4][4], accU[2][4][4];
#pragma unroll
    for (int i = 0; i < 2; i++)
#pragma unroll
        for (int j = 0; j < 4; j++)
#pragma unroll
            for (int k = 0; k < 4; k++) { accG[i][j][k] = 0.0f; accU[i][j][k] = 0.0f; }

    const int KB = H_DIM / TK;

#define G1_ISSUE(kb, st) do { \
        uint32_t b_ = sdst + (uint32_t)(st) * ST1; \
        int kk_ = (kb) * TK; \
        cpa16(b_ +     0, axh + kk_, asz); \
        cpa16(b_ + 10240, axl + kk_, asz); \
        cpa16(b_ + 20480, agh + kk_, 16); \
        cpa16(b_ + 30720, agl + kk_, 16); \
        cpa16(b_ + 40960, auh + kk_, 16); \
        cpa16(b_ + 51200, aul + kk_, 16); \
        CP_COMMIT(); \
    } while (0)

    G1_ISSUE(0, 0);
    G1_ISSUE(1, 1);

    for (int kb = 0; kb < KB; kb++) {
        if (kb + 1 < KB) { CP_WAIT1(); } else { CP_WAIT0(); }
        __syncthreads();
        if (kb + 2 < KB) G1_ISSUE(kb + 2, (kb + 2) % NSTAGE);

        const uint32_t s0 = sb + 512 + (uint32_t)((kb % NSTAGE) * ST1);
        const uint32_t sA = s0 + aoff;
        const uint32_t sB = s0 + boff;

#pragma unroll
        for (int k16 = 0; k16 < 2; k16++) {
            const uint32_t ka = (uint32_t)(k16 * 32);
            uint32_t aH[2][4], aL[2][4];
            LDSM4(aH[0], sA + ka);
            LDSM4(aH[1], sA + 16 * RS + ka);
            LDSM4(aL[0], sA + 10240 + ka);
            LDSM4(aL[1], sA + 10240 + 16 * RS + ka);
#pragma unroll
            for (int nt2 = 0; nt2 < 2; nt2++) {
                const uint32_t bn = sB + (uint32_t)(nt2 * 16 * RS) + ka;
                uint32_t b[4];
                // gate hi: pairs with aH and aL
                LDSM4(b, bn + 20480);
                MMA(accG[0][nt2 * 2 + 0], aH[0], b[0], b[1]);
                MMA(accG[0][nt2 * 2 + 1], aH[0], b[2], b[3]);
                MMA(accG[1][nt2 * 2 + 0], aH[1], b[0], b[1]);
                MMA(accG[1][nt2 * 2 + 1], aH[1], b[2], b[3]);
                MMA(accG[0][nt2 * 2 + 0], aL[0], b[0], b[1]);
                MMA(accG[0][nt2 * 2 + 1], aL[0], b[2], b[3]);
                MMA(accG[1][nt2 * 2 + 0], aL[1], b[0], b[1]);
                MMA(accG[1][nt2 * 2 + 1], aL[1], b[2], b[3]);
                // gate lo: pairs with aH only
                LDSM4(b, bn + 30720);
                MMA(accG[0][nt2 * 2 + 0], aH[0], b[0], b[1]);
                MMA(accG[0][nt2 * 2 + 1], aH[0], b[2], b[3]);
                MMA(accG[1][nt2 * 2 + 0], aH[1], b[0], b[1]);
                MMA(accG[1][nt2 * 2 + 1], aH[1], b[2], b[3]);
                // up hi
                LDSM4(b, bn + 40960);
                MMA(accU[0][nt2 * 2 + 0], aH[0], b[0], b[1]);
                MMA(accU[0][nt2 * 2 + 1], aH[0], b[2], b[3]);
                MMA(accU[1][nt2 * 2 + 0], aH[1], b[0], b[1]);
                MMA(accU[1][nt2 * 2 + 1], aH[1], b[2], b[3]);
                MMA(accU[0][nt2 * 2 + 0], aL[0], b[0], b[1]);
                MMA(accU[0][nt2 * 2 + 1], aL[0], b[2], b[3]);
                MMA(accU[1][nt2 * 2 + 0], aL[1], b[0], b[1]);
                MMA(accU[1][nt2 * 2 + 1], aL[1], b[2], b[3]);
                // up lo
                LDSM4(b, bn + 51200);
                MMA(accU[0][nt2 * 2 + 0], aH[0], b[0], b[1]);
                MMA(accU[0][nt2 * 2 + 1], aH[0], b[2], b[3]);
                MMA(accU[1][nt2 * 2 + 0], aH[1], b[0], b[1]);
                MMA(accU[1][nt2 * 2 + 1], aH[1], b[2], b[3]);
            }
        }
    }
#undef G1_ISSUE

    // epilogue: silu(g)*u -> inter hi/lo
#pragma unroll
    for (int mt = 0; mt < 2; mt++) {
#pragma unroll
        for (int half = 0; half < 2; half++) {
            int rloc = wm * 32 + mt * 16 + lr + half * 8;
            int r = rowBase + rloc;
            if (r >= cnt) continue;
            size_t base = (size_t)(off + r) * I_DIM + n0 + wn * 32 + (lc2 >> 1);
#pragma unroll
            for (int nt = 0; nt < 4; nt++) {
                float g0 = accG[mt][nt][half * 2 + 0], u0 = accU[mt][nt][half * 2 + 0];
                float g1 = accG[mt][nt][half * 2 + 1], u1 = accU[mt][nt][half * 2 + 1];
                float v0 = (g0 / (1.0f + __expf(-g0))) * u0;
                float v1 = (g1 / (1.0f + __expf(-g1))) * u1;
                uint32_t lo;
                uint32_t hi = pack2(v0, v1, lo);
                *(uint32_t*)(g_ih + base + nt * 8) = hi;
                *(uint32_t*)(g_il + base + nt * 8) = lo;
            }
        }
    }
}

// ---------------- GEMM2 ----------------
// grid: x = row-tile (fastest), y = N-tile, z = expert
// stage tiles: AH 0, AL 10240, BH 20480, BL 30720
#define ST2 (4 * TM * RS)                 // 40960
#define G2_SMEM (1024 + NSTAGE * ST2)     // 123904

__global__ void __launch_bounds__(NTHREADS, 1)
gemm2_kernel(float* __restrict__ out)
{
    const int e = blockIdx.z;
    const int cnt = g_cnt[e];
    const int rowBase = blockIdx.x * TM;
    if (rowBase >= cnt) return;
    const int off = g_off[e];
    const int n0 = blockIdx.y * TN;

    extern __shared__ char smem[];
    int*   s_tok = (int*)smem;
    float* s_wgt = (float*)(smem + 512);
    const uint32_t sb = smem_u32(smem);

    const int tid = threadIdx.x, wid = tid >> 5, lane = tid & 31;
    const int wm = wid >> 2, wn = wid & 3;
    const int lr = lane >> 2, lc2 = (lane & 3) << 2;
    const int lg = lane >> 3, l7 = lane & 7;

    if (tid < TM) {
        int r = rowBase + tid;
        s_tok[tid] = (r < cnt) ? g_tok[off + r] : -1;
        s_wgt[tid] = (r < cnt) ? g_wgt[off + r] : 0.0f;
    }
    __syncthreads();

    const int srow = tid >> 2, sch = tid & 3;
    const int selem = sch * 8;
    const uint32_t sdst = sb + 1024 + (uint32_t)(srow * RS + sch * 16);
    const int valid = (rowBase + srow < cnt);
    const int asz = valid ? 16 : 0;
    const size_t arow = (size_t)(off + (valid ? rowBase + srow : 0)) * I_DIM + selem;
    const size_t brow = ((size_t)e * H_DIM + n0 + srow) * I_DIM + selem;
    const __nv_bfloat16* aih = g_ih + arow;
    const __nv_bfloat16* ail = g_il + arow;
    const __nv_bfloat16* adh = g_dh + brow;
    const __nv_bfloat16* adl = g_dl + brow;

    const uint32_t aoff = (uint32_t)((wm * 32 + ((lg & 1) << 3) + l7) * RS + ((lg >> 1) << 4));
    const uint32_t boff = (uint32_t)((wn * 32 + ((lg >> 1) << 3) + l7) * RS + ((lg & 1) << 4));

    float acc[2][4][4];
#pragma unroll
    for (int i = 0; i < 2; i++)
#pragma unroll
        for (int j = 0; j < 4; j++)
#pragma unroll
            for (int k = 0; k < 4; k++) acc[i][j][k] = 0.0f;

    const int KB = I_DIM / TK;

#define G2_ISSUE(kb, st) do { \
        uint32_t b_ = sdst + (uint32_t)(st) * ST2; \
        int kk_ = (kb) * TK; \
        cpa16(b_ +     0, aih + kk_, asz); \
        cpa16(b_ + 10240, ail + kk_, asz); \
        cpa16(b_ + 20480, adh + kk_, 16); \
        cpa16(b_ + 30720, adl + kk_, 16); \
        CP_COMMIT(); \
    } while (0)

    G2_ISSUE(0, 0);
    G2_ISSUE(1, 1);

    for (int kb = 0; kb < KB; kb++) {
        if (kb + 1 < KB) { CP_WAIT1(); } else { CP_WAIT0(); }
        __syncthreads();
        if (kb + 2 < KB) G2_ISSUE(kb + 2, (kb + 2) % NSTAGE);

        const uint32_t s0 = sb + 1024 + (uint32_t)((kb % NSTAGE) * ST2);
        const uint32_t sA = s0 + aoff;
        const uint32_t sB = s0 + boff;

#pragma unroll
        for (int k16 = 0; k16 < 2; k16++) {
            const uint32_t ka = (uint32_t)(k16 * 32);
            uint32_t aH[2][4], aL[2][4];
            LDSM4(aH[0], sA + ka);
            LDSM4(aH[1], sA + 16 * RS + ka);
            LDSM4(aL[0], sA + 10240 + ka);
            LDSM4(aL[1], sA + 10240 + 16 * RS + ka);
#pragma unroll
            for (int nt2 = 0; nt2 < 2; nt2++) {
                const uint32_t bn = sB + (uint32_t)(nt2 * 16 * RS) + ka;
                uint32_t b[4];
                // down hi: aH + aL
                LDSM4(b, bn + 20480);
                MMA(acc[0][nt2 * 2 + 0], aH[0], b[0], b[1]);
                MMA(acc[0][nt2 * 2 + 1], aH[0], b[2], b[3]);
                MMA(acc[1][nt2 * 2 + 0], aH[1], b[0], b[1]);
                MMA(acc[1][nt2 * 2 + 1], aH[1], b[2], b[3]);
                MMA(acc[0][nt2 * 2 + 0], aL[0], b[0], b[1]);
                MMA(acc[0][nt2 * 2 + 1], aL[0], b[2], b[3]);
                MMA(acc[1][nt2 * 2 + 0], aL[1], b[0], b[1]);
                MMA(acc[1][nt2 * 2 + 1], aL[1], b[2], b[3]);
                // down lo: aH only
                LDSM4(b, bn + 30720);
                MMA(acc[0][nt2 * 2 + 0], aH[0], b[0], b[1]);
                MMA(acc[0][nt2 * 2 + 1], aH[0], b[2], b[3]);
                MMA(acc[1][nt2 * 2 + 0], aH[1], b[0], b[1]);
                MMA(acc[1][nt2 * 2 + 1], aH[1], b[2], b[3]);
            }
        }
    }
#undef G2_ISSUE

    // epilogue: weighted scatter-add
#pragma unroll
    for (int mt = 0; mt < 2; mt++) {
#pragma unroll
        for (int half = 0; half < 2; half++) {
            int rloc = wm * 32 + mt * 16 + lr + half * 8;
            int t = s_tok[rloc];
            if (t < 0) continue;
            float w = s_wgt[rloc];
            float* dst = out + (size_t)t * H_DIM + n0 + wn * 32 + (lc2 >> 1);
#pragma unroll
            for (int nt = 0; nt < 4; nt++) {
                atomicAdd(dst + nt * 8 + 0, w * acc[mt][nt][half * 2 + 0]);
                atomicAdd(dst + nt * 8 + 1, w * acc[mt][nt][half * 2 + 1]);
            }
        }
    }
}

// ---------------- launch ----------------
extern "C" void kernel_launch(void* const* d_in, const int* in_sizes, int n_in,
                              void* d_out, int out_size)
{
    const float*    x    = (const float*)d_in[0];
    const unsigned* idx  = (const unsigned*)d_in[1];
    const float*    wts  = (const float*)d_in[2];
    const float*    gate = (const float*)d_in[3];
    const float*    up   = (const float*)d_in[4];
    const float*    down = (const float*)d_in[5];
    float* out = (float*)d_out;

    static int attr_done = 0;
    if (!attr_done) {
        cudaFuncSetAttribute(gemm1_kernel, cudaFuncAttributeMaxDynamicSharedMemorySize, G1_SMEM);
        cudaFuncSetAttribute(gemm2_kernel, cudaFuncAttributeMaxDynamicSharedMemorySize, G2_SMEM);
        attr_done = 1;
    }

    cudaMemsetAsync(out, 0, (size_t)out_size * sizeof(float));
    route_kernel<<<1, 256>>>(idx, wts);

    __nv_bfloat16 *gh, *gl, *uh, *ul, *dh, *dl, *xh, *xl;
    cudaGetSymbolAddress((void**)&gh, g_gh); cudaGetSymbolAddress((void**)&gl, g_gl);
    cudaGetSymbolAddress((void**)&uh, g_uh); cudaGetSymbolAddress((void**)&ul, g_ul);
    cudaGetSymbolAddress((void**)&dh, g_dh); cudaGetSymbolAddress((void**)&dl, g_dl);
    cudaGetSymbolAddress((void**)&xh, g_xh); cudaGetSymbolAddress((void**)&xl, g_xl);

    const size_t nw = NW;
    const size_t nx = (size_t)T_NUM * H_DIM;
    convert_kernel<<<(unsigned)(nw / 1024), 256>>>(gate, gh, gl, nw);
    convert_kernel<<<(unsigned)(nw / 1024), 256>>>(up,   uh, ul, nw);
    convert_kernel<<<(unsigned)(nw / 1024), 256>>>(down, dh, dl, nw);
    convert_kernel<<<(unsigned)(nx / 1024), 256>>>(x,    xh, xl, nx);

    // grid: x = row-tile (adjacent CTAs share weight panel -> L2 reuse), y = N-tile
    gemm1_kernel<<<dim3(T_NUM / TM, I_DIM / TN, E_NUM), NTHREADS, G1_SMEM>>>();
    gemm2_kernel<<<dim3(T_NUM / TM, H_DIM / TN, E_NUM), NTHREADS, G2_SMEM>>>(out);
}